// round 1
// baseline (speedup 1.0000x reference)
#include <cuda_runtime.h>
#include <math.h>

#define NITER 50
#define TOLV 1e-3f
#define STALL_EPSV 1e-6f
#define TPB 256
#define EPT 4   // elements per thread

// Scratch (no allocation allowed): per-iteration global max |residual| as uint bits, and T.
__device__ unsigned int g_max[NITER];
__device__ int g_T;

__global__ void init_kernel() {
    int t = threadIdx.x;
    if (t < NITER) g_max[t] = 0u;
    if (t == NITER) g_T = NITER;
}

// ---------------------------------------------------------------------------
// Phase A: full 50-step unfrozen simulation, register-resident.
// Records per-iteration global max(|residual|) and writes 50-step flow to out.
// ---------------------------------------------------------------------------
__global__ __launch_bounds__(TPB)
void phaseA(const float* __restrict__ speed,
            const float* __restrict__ pos_s,
            const float* __restrict__ pos_e,
            const float* __restrict__ sp,   // supply_params[4]
            const float* __restrict__ ep,   // exhaust_params[4]
            const float* __restrict__ fp,   // fan_params[2]
            float* __restrict__ out,
            int B, int stride)
{
    __shared__ float smax[NITER * (TPB / 32)];
    const int tid  = blockIdx.x * blockDim.x + threadIdx.x;
    const int warp = threadIdx.x >> 5;
    const int lane = threadIdx.x & 31;

    const float F = fp[0], P = fp[1];
    const float flow_scale = F / (P + 1e-6f);
    const float lo = 0.01f, hi = 1.5f * F;
    const float pF2 = P / (F * F);

    const float Rds = expf(sp[0]), Ros = expf(sp[2]), ks = sp[3];
    const float Rde = expf(ep[0]), Roe = expf(ep[2]), ke = ep[3];
    const float L = fabsf(sp[1]) + fabsf(ep[1]);

    float f[EPT], A[EPT], C[EPT];
    bool  v[EPT];
#pragma unroll
    for (int e = 0; e < EPT; e++) {
        int idx = tid + e * stride;
        v[e] = (idx < B);
        int j = v[e] ? idx : 0;
        float s = speed[j];
        A[e] = P * s * s;
        C[e] = pF2 + (Rds + Ros * expf(ks * (1.0f - pos_s[j])))
                   + (Rde + Roe * expf(ke * (1.0f - pos_e[j])));
        f[e] = s * F;
    }

    for (int i = 0; i < NITER; i++) {
        float alpha = fmaxf(0.5f * powf(0.95f, (float)i), 0.05f);
        float lmax = 0.0f;
#pragma unroll
        for (int e = 0; e < EPT; e++) {
            float r = fmaf(-L, f[e], fmaf(-C[e], f[e] * f[e], A[e]));
            if (v[e]) lmax = fmaxf(lmax, fabsf(r));
            float fn = f[e] + (alpha * r) * flow_scale;
            f[e] = fminf(fmaxf(fn, lo), hi);
        }
#pragma unroll
        for (int o = 16; o > 0; o >>= 1)
            lmax = fmaxf(lmax, __shfl_xor_sync(0xffffffffu, lmax, o));
        if (lane == 0) smax[i * (TPB / 32) + warp] = lmax;
    }
    __syncthreads();

    for (int j = threadIdx.x; j < NITER; j += blockDim.x) {
        float m = smax[j * (TPB / 32)];
#pragma unroll
        for (int w = 1; w < TPB / 32; w++)
            m = fmaxf(m, smax[j * (TPB / 32) + w]);
        atomicMax(&g_max[j], __float_as_uint(m));  // all values >= 0: uint order == float order
    }

#pragma unroll
    for (int e = 0; e < EPT; e++) {
        int idx = tid + e * stride;
        if (idx < B) out[idx] = f[e];
    }
}

// ---------------------------------------------------------------------------
// Phase B: scalar replay of the done/stall state machine -> T.
// ---------------------------------------------------------------------------
__global__ void phaseB() {
    bool done = false;
    float prev = INFINITY;
    int stall = 0;
    int T = NITER;
    for (int i = 0; i < NITER; i++) {
        float me = __uint_as_float(g_max[i]);
        bool done_tol = done || (me < TOLV);
        int sn = (fabsf(me - prev) < STALL_EPSV) ? (stall + 1) : 0;
        if (done_tol) sn = stall;
        bool dn = done_tol || (sn > 10);
        if (dn) { T = i; break; }
        stall = sn;
        prev = me;
    }
    g_T = T;
}

// ---------------------------------------------------------------------------
// Phase C: if T < 50, re-simulate exactly T steps (no reduction needed).
// ---------------------------------------------------------------------------
__global__ __launch_bounds__(TPB)
void phaseC(const float* __restrict__ speed,
            const float* __restrict__ pos_s,
            const float* __restrict__ pos_e,
            const float* __restrict__ sp,
            const float* __restrict__ ep,
            const float* __restrict__ fp,
            float* __restrict__ out,
            int B, int stride)
{
    const int T = g_T;
    if (T >= NITER) return;  // Phase A output already final

    const int tid = blockIdx.x * blockDim.x + threadIdx.x;
    const float F = fp[0], P = fp[1];
    const float flow_scale = F / (P + 1e-6f);
    const float lo = 0.01f, hi = 1.5f * F;
    const float pF2 = P / (F * F);

    const float Rds = expf(sp[0]), Ros = expf(sp[2]), ks = sp[3];
    const float Rde = expf(ep[0]), Roe = expf(ep[2]), ke = ep[3];
    const float L = fabsf(sp[1]) + fabsf(ep[1]);

    float f[EPT], A[EPT], C[EPT];
    bool  v[EPT];
#pragma unroll
    for (int e = 0; e < EPT; e++) {
        int idx = tid + e * stride;
        v[e] = (idx < B);
        int j = v[e] ? idx : 0;
        float s = speed[j];
        A[e] = P * s * s;
        C[e] = pF2 + (Rds + Ros * expf(ks * (1.0f - pos_s[j])))
                   + (Rde + Roe * expf(ke * (1.0f - pos_e[j])));
        f[e] = s * F;
    }

    for (int i = 0; i < T; i++) {
        float alpha = fmaxf(0.5f * powf(0.95f, (float)i), 0.05f);
#pragma unroll
        for (int e = 0; e < EPT; e++) {
            float r = fmaf(-L, f[e], fmaf(-C[e], f[e] * f[e], A[e]));
            float fn = f[e] + (alpha * r) * flow_scale;
            f[e] = fminf(fmaxf(fn, lo), hi);
        }
    }

#pragma unroll
    for (int e = 0; e < EPT; e++) {
        int idx = tid + e * stride;
        if (idx < B) out[idx] = f[e];
    }
}

// ---------------------------------------------------------------------------
// Launch: init -> phaseA -> phaseB -> phaseC, all on the capture stream.
// Inputs (metadata order): fan_speed, supply_damper_pos, exhaust_damper_pos,
//                          supply_params[4], exhaust_params[4], fan_params[2]
// ---------------------------------------------------------------------------
extern "C" void kernel_launch(void* const* d_in, const int* in_sizes, int n_in,
                              void* d_out, int out_size)
{
    const float* speed = (const float*)d_in[0];
    const float* pos_s = (const float*)d_in[1];
    const float* pos_e = (const float*)d_in[2];
    const float* sp    = (const float*)d_in[3];
    const float* ep    = (const float*)d_in[4];
    const float* fp    = (const float*)d_in[5];
    float* out = (float*)d_out;

    const int B = in_sizes[0];
    const int threads_needed = (B + EPT - 1) / EPT;
    const int blocks = (threads_needed + TPB - 1) / TPB;
    const int stride = blocks * TPB;

    init_kernel<<<1, 64>>>();
    phaseA<<<blocks, TPB>>>(speed, pos_s, pos_e, sp, ep, fp, out, B, stride);
    phaseB<<<1, 1>>>();
    phaseC<<<blocks, TPB>>>(speed, pos_s, pos_e, sp, ep, fp, out, B, stride);
}

// round 2
// speedup vs baseline: 1.8934x; 1.8934x over previous
#include <cuda_runtime.h>
#include <math.h>

#define NITER 50
#define TOLV 1e-3f
#define STALL_EPSV 1e-6f
#define TPB 256
#define EPT 4            // elements per thread
#define NPAIR (EPT / 2)  // f32x2 pairs per thread
#define NWARP (TPB / 32)

// Scratch (no allocation allowed)
__device__ unsigned int g_max[NITER];
__device__ int g_T;

// ---- packed f32x2 helpers (sm_100+) ----
__device__ __forceinline__ unsigned long long pack2(float a, float b) {
    unsigned long long r;
    asm("mov.b64 %0, {%1, %2};" : "=l"(r) : "f"(a), "f"(b));
    return r;
}
__device__ __forceinline__ void unpack2(unsigned long long v, float& a, float& b) {
    asm("mov.b64 {%0, %1}, %2;" : "=f"(a), "=f"(b) : "l"(v));
}
__device__ __forceinline__ unsigned long long mul2(unsigned long long a, unsigned long long b) {
    unsigned long long r;
    asm("mul.rn.f32x2 %0, %1, %2;" : "=l"(r) : "l"(a), "l"(b));
    return r;
}
__device__ __forceinline__ unsigned long long fma2(unsigned long long a, unsigned long long b,
                                                   unsigned long long c) {
    unsigned long long r;
    asm("fma.rn.f32x2 %0, %1, %2, %3;" : "=l"(r) : "l"(a), "l"(b), "l"(c));
    return r;
}
__device__ __forceinline__ unsigned int warp_redux_max_u32(unsigned int v) {
    unsigned int r;
    asm("redux.sync.max.u32 %0, %1, 0xffffffff;" : "=r"(r) : "r"(v));
    return r;
}

__global__ void init_kernel() {
    int t = threadIdx.x;
    if (t < NITER) g_max[t] = 0u;
    if (t == NITER) g_T = NITER;
}

// ---------------------------------------------------------------------------
// Phase A: full 50-step unfrozen simulation, packed f32x2, register-resident.
// ---------------------------------------------------------------------------
__global__ __launch_bounds__(TPB)
void phaseA(const float* __restrict__ speed,
            const float* __restrict__ pos_s,
            const float* __restrict__ pos_e,
            const float* __restrict__ sp,
            const float* __restrict__ ep,
            const float* __restrict__ fp,
            float* __restrict__ out,
            int B, int stride)
{
    __shared__ unsigned int smax[NITER * NWARP];
    const int tid  = blockIdx.x * blockDim.x + threadIdx.x;
    const int warp = threadIdx.x >> 5;
    const int lane = threadIdx.x & 31;

    const float F = fp[0], P = fp[1];
    const float flow_scale = F / (P + 1e-6f);
    const float lo = 0.01f, hi = 1.5f * F;
    const float pF2 = P / (F * F);

    const float Rds = expf(sp[0]), Ros = expf(sp[2]), ks = sp[3];
    const float Rde = expf(ep[0]), Roe = expf(ep[2]), ke = ep[3];
    const float L = fabsf(sp[1]) + fabsf(ep[1]);
    const unsigned long long nL2 = pack2(-L, -L);

    // Per-element setup: f = s*F, A = P*s^2, nC = -(P/F^2 + Rs + Re)
    unsigned long long f2[NPAIR], A2[NPAIR], nC2[NPAIR];
#pragma unroll
    for (int p = 0; p < NPAIR; p++) {
        float fe[2], Ae[2], nCe[2];
#pragma unroll
        for (int h = 0; h < 2; h++) {
            int e = 2 * p + h;
            int idx = tid + e * stride;
            if (idx < B) {
                float s = speed[idx];
                Ae[h] = P * s * s;
                nCe[h] = -(pF2 + (Rds + Ros * expf(ks * (1.0f - pos_s[idx])))
                               + (Rde + Roe * expf(ke * (1.0f - pos_e[idx]))));
                fe[h] = s * F;
            } else {
                // inert element: residual identically 0, flow pinned at lo
                fe[h] = lo; nCe[h] = 0.0f; Ae[h] = L * lo;
            }
        }
        f2[p]  = pack2(fe[0], fe[1]);
        A2[p]  = pack2(Ae[0], Ae[1]);
        nC2[p] = pack2(nCe[0], nCe[1]);
    }

    float a = 0.5f;  // 0.5 * 0.95^i via iterative multiply
    for (int i = 0; i < NITER; i++) {
        float alpha = fmaxf(a, 0.05f);
        float af = alpha * flow_scale;
        a *= 0.95f;
        const unsigned long long af2 = pack2(af, af);
        float lmax = 0.0f;
#pragma unroll
        for (int p = 0; p < NPAIR; p++) {
            unsigned long long t2 = mul2(f2[p], f2[p]);
            unsigned long long r2 = fma2(nC2[p], t2, A2[p]);
            r2 = fma2(nL2, f2[p], r2);
            unsigned long long fn2 = fma2(r2, af2, f2[p]);
            float r0, r1; unpack2(r2, r0, r1);
            lmax = fmaxf(lmax, fabsf(r0));
            lmax = fmaxf(lmax, fabsf(r1));
            float x0, x1; unpack2(fn2, x0, x1);
            x0 = fminf(fmaxf(x0, lo), hi);
            x1 = fminf(fmaxf(x1, lo), hi);
            f2[p] = pack2(x0, x1);
        }
        // lmax >= 0: uint bit order == float order
        unsigned int red = warp_redux_max_u32(__float_as_uint(lmax));
        if (lane == 0) smax[i * NWARP + warp] = red;
    }
    __syncthreads();

    for (int j = threadIdx.x; j < NITER; j += blockDim.x) {
        unsigned int m = smax[j * NWARP];
#pragma unroll
        for (int w = 1; w < NWARP; w++) m = max(m, smax[j * NWARP + w]);
        atomicMax(&g_max[j], m);
    }

#pragma unroll
    for (int p = 0; p < NPAIR; p++) {
        float x0, x1; unpack2(f2[p], x0, x1);
        int i0 = tid + (2 * p) * stride;
        int i1 = tid + (2 * p + 1) * stride;
        if (i0 < B) out[i0] = x0;
        if (i1 < B) out[i1] = x1;
    }
}

// ---------------------------------------------------------------------------
// Phase B: scalar replay of the done/stall state machine -> T.
// ---------------------------------------------------------------------------
__global__ void phaseB() {
    bool done = false;
    float prev = INFINITY;
    int stall = 0;
    int T = NITER;
    for (int i = 0; i < NITER; i++) {
        float me = __uint_as_float(g_max[i]);
        bool done_tol = done || (me < TOLV);
        int sn = (fabsf(me - prev) < STALL_EPSV) ? (stall + 1) : 0;
        if (done_tol) sn = stall;
        bool dn = done_tol || (sn > 10);
        if (dn) { T = i; break; }
        stall = sn;
        prev = me;
    }
    g_T = T;
}

// ---------------------------------------------------------------------------
// Phase C: if T < 50, re-simulate exactly T steps and overwrite out.
// ---------------------------------------------------------------------------
__global__ __launch_bounds__(TPB)
void phaseC(const float* __restrict__ speed,
            const float* __restrict__ pos_s,
            const float* __restrict__ pos_e,
            const float* __restrict__ sp,
            const float* __restrict__ ep,
            const float* __restrict__ fp,
            float* __restrict__ out,
            int B, int stride)
{
    const int T = g_T;
    if (T >= NITER) return;  // Phase A output already final

    const int tid = blockIdx.x * blockDim.x + threadIdx.x;
    const float F = fp[0], P = fp[1];
    const float flow_scale = F / (P + 1e-6f);
    const float lo = 0.01f, hi = 1.5f * F;
    const float pF2 = P / (F * F);

    const float Rds = expf(sp[0]), Ros = expf(sp[2]), ks = sp[3];
    const float Rde = expf(ep[0]), Roe = expf(ep[2]), ke = ep[3];
    const float L = fabsf(sp[1]) + fabsf(ep[1]);
    const unsigned long long nL2 = pack2(-L, -L);

    unsigned long long f2[NPAIR], A2[NPAIR], nC2[NPAIR];
#pragma unroll
    for (int p = 0; p < NPAIR; p++) {
        float fe[2], Ae[2], nCe[2];
#pragma unroll
        for (int h = 0; h < 2; h++) {
            int e = 2 * p + h;
            int idx = tid + e * stride;
            if (idx < B) {
                float s = speed[idx];
                Ae[h] = P * s * s;
                nCe[h] = -(pF2 + (Rds + Ros * expf(ks * (1.0f - pos_s[idx])))
                               + (Rde + Roe * expf(ke * (1.0f - pos_e[idx]))));
                fe[h] = s * F;
            } else {
                fe[h] = lo; nCe[h] = 0.0f; Ae[h] = L * lo;
            }
        }
        f2[p]  = pack2(fe[0], fe[1]);
        A2[p]  = pack2(Ae[0], Ae[1]);
        nC2[p] = pack2(nCe[0], nCe[1]);
    }

    float a = 0.5f;
    for (int i = 0; i < T; i++) {
        float alpha = fmaxf(a, 0.05f);
        float af = alpha * flow_scale;
        a *= 0.95f;
        const unsigned long long af2 = pack2(af, af);
#pragma unroll
        for (int p = 0; p < NPAIR; p++) {
            unsigned long long t2 = mul2(f2[p], f2[p]);
            unsigned long long r2 = fma2(nC2[p], t2, A2[p]);
            r2 = fma2(nL2, f2[p], r2);
            unsigned long long fn2 = fma2(r2, af2, f2[p]);
            float x0, x1; unpack2(fn2, x0, x1);
            x0 = fminf(fmaxf(x0, lo), hi);
            x1 = fminf(fmaxf(x1, lo), hi);
            f2[p] = pack2(x0, x1);
        }
    }

#pragma unroll
    for (int p = 0; p < NPAIR; p++) {
        float x0, x1; unpack2(f2[p], x0, x1);
        int i0 = tid + (2 * p) * stride;
        int i1 = tid + (2 * p + 1) * stride;
        if (i0 < B) out[i0] = x0;
        if (i1 < B) out[i1] = x1;
    }
}

// ---------------------------------------------------------------------------
// Inputs (metadata order): fan_speed, supply_damper_pos, exhaust_damper_pos,
//                          supply_params[4], exhaust_params[4], fan_params[2]
// ---------------------------------------------------------------------------
extern "C" void kernel_launch(void* const* d_in, const int* in_sizes, int n_in,
                              void* d_out, int out_size)
{
    const float* speed = (const float*)d_in[0];
    const float* pos_s = (const float*)d_in[1];
    const float* pos_e = (const float*)d_in[2];
    const float* sp    = (const float*)d_in[3];
    const float* ep    = (const float*)d_in[4];
    const float* fp    = (const float*)d_in[5];
    float* out = (float*)d_out;

    const int B = in_sizes[0];
    const int threads_needed = (B + EPT - 1) / EPT;
    const int blocks = (threads_needed + TPB - 1) / TPB;
    const int stride = blocks * TPB;

    init_kernel<<<1, 64>>>();
    phaseA<<<blocks, TPB>>>(speed, pos_s, pos_e, sp, ep, fp, out, B, stride);
    phaseB<<<1, 1>>>();
    phaseC<<<blocks, TPB>>>(speed, pos_s, pos_e, sp, ep, fp, out, B, stride);
}